// round 12
// baseline (speedup 1.0000x reference)
#include <cuda_runtime.h>
#include <cuda_bf16.h>
#include <math.h>
#include <stdint.h>

#define N_EL    16
#define N_NUC   4
#define N_FEATS 32
#define N_EN    64
#define N_EE    120
#define N_PAIRS 184
#define HIDDEN  64
#define ROWS    256
#define THREADS 512
#define CK      64
#define NCHUNK  92

// ---- SMEM layout (bytes) ----
// Each buffer: A_H 256x128, A_L 256x128, B_H 64x128, B_L 64x128 = 81920
#define BUFSZ   81920
#define A_Ho    0
#define A_Lo    32768
#define B_Ho    65536
#define B_Lo    73728
#define OFF_RS  163840             // 256*49*4 = 50176
#define OFF_W2  81920              // overlay on buf1 after mainloop (16384)
#define OFF_H   0                  // overlay on buf0 after mainloop (256*66*4)
#define OFF_ABC   214016
#define OFF_COORD 214528
#define OFF_CHG   214576
#define OFF_B1    214592
#define OFF_B2    214848
#define OFF_W3    215104
#define OFF_B3    215360
#define OFF_PI    215376
#define OFF_PJ    215856
#define SMEM_BYTES 216448

#define LOG2E 1.4426950408889634f

__device__ __forceinline__ float sspf(float x) {
    return fmaxf(x, 0.0f) + log1pf(expf(-fabsf(x))) - 0.69314718055994531f;
}
__device__ __forceinline__ float ex2(float x) {
    float r; asm("ex2.approx.ftz.f32 %0, %1;" : "=f"(r) : "f"(x)); return r;
}
__device__ __forceinline__ uint32_t smem_u32(const void* p) {
    uint32_t a;
    asm("{ .reg .u64 t; cvta.to.shared.u64 t, %1; cvt.u32.u64 %0, t; }"
        : "=r"(a) : "l"(p));
    return a;
}
__device__ __forceinline__ void ldsm4(uint32_t* r, uint32_t a) {
    asm volatile("ldmatrix.sync.aligned.m8n8.x4.shared.b16 {%0,%1,%2,%3}, [%4];"
        : "=r"(r[0]), "=r"(r[1]), "=r"(r[2]), "=r"(r[3]) : "r"(a));
}
__device__ __forceinline__ void ldsm4t(uint32_t* r, uint32_t a) {
    asm volatile("ldmatrix.sync.aligned.m8n8.x4.trans.shared.b16 {%0,%1,%2,%3}, [%4];"
        : "=r"(r[0]), "=r"(r[1]), "=r"(r[2]), "=r"(r[3]) : "r"(a));
}
__device__ __forceinline__ void mma16816(float* c, const uint32_t* a, const uint32_t* b) {
    asm volatile("mma.sync.aligned.m16n8k16.row.col.f32.bf16.bf16.f32 "
        "{%0,%1,%2,%3}, {%4,%5,%6,%7}, {%8,%9}, {%0,%1,%2,%3};"
        : "+f"(c[0]), "+f"(c[1]), "+f"(c[2]), "+f"(c[3])
        : "r"(a[0]), "r"(a[1]), "r"(a[2]), "r"(a[3]), "r"(b[0]), "r"(b[1]));
}
// hi = bf16-truncate of (a,b) packed; lo = rn-bf16 of residuals packed
__device__ __forceinline__ void pack_hilo(float a, float b, uint32_t& hp, uint32_t& lp) {
    uint32_t ua = __float_as_uint(a), ub = __float_as_uint(b);
    hp = __byte_perm(ua, ub, 0x7632);
    float ha = __uint_as_float(ua & 0xffff0000u);
    float hb = __uint_as_float(ub & 0xffff0000u);
    __nv_bfloat162 l2 = __floats2bfloat162_rn(a - ha, b - hb);
    lp = *reinterpret_cast<uint32_t*>(&l2);
}

__global__ __launch_bounds__(THREADS, 1)
void wfnet_kernel(const float* __restrict__ rs,
                  const float* __restrict__ coords,
                  const float* __restrict__ charges,
                  const float* __restrict__ W1,
                  const float* __restrict__ b1,
                  const float* __restrict__ W2,
                  const float* __restrict__ b2,
                  const float* __restrict__ W3,
                  const float* __restrict__ b3,
                  float* __restrict__ out)
{
    extern __shared__ char smem[];
    const uint32_t sbase = smem_u32(smem);

    float4* s_abc  = (float4*)(smem + OFF_ABC);
    float* s_coord = (float*)(smem + OFF_COORD);
    float* s_chg   = (float*)(smem + OFF_CHG);
    float* s_b1    = (float*)(smem + OFF_B1);
    float* s_b2    = (float*)(smem + OFF_B2);
    float* s_w3    = (float*)(smem + OFF_W3);
    float* s_b3    = (float*)(smem + OFF_B3);
    int*   s_pi    = (int*)  (smem + OFF_PI);
    int*   s_pj    = (int*)  (smem + OFF_PJ);
    float* s_rs    = (float*)(smem + OFF_RS);
    float* s_w2    = (float*)(smem + OFF_W2);
    float* s_h     = (float*)(smem + OFF_H);

    const int tid  = threadIdx.x;
    const int b0   = blockIdx.x * ROWS;
    const int lane = tid & 31;
    const int warp = tid >> 5;

    // ---- setup ----
    if (tid < N_FEATS) {
        float q   = (float)tid / 31.0f;
        float mu  = 10.0f * q * q;
        float sig = (1.0f + 10.0f * q) * (1.0f / 7.0f);
        float a   = -LOG2E / (sig * sig);
        s_abc[tid] = make_float4(a, -2.0f * mu * a, a * mu * mu, 0.0f);
    }
    if (tid < 12) s_coord[tid] = coords[tid];
    if (tid < 4)  s_chg[tid]   = charges[tid];
    if (tid < HIDDEN) { s_b1[tid] = b1[tid]; s_b2[tid] = b2[tid]; s_w3[tid] = W3[tid]; }
    if (tid == 0) s_b3[0] = b3[0];
    if (tid < N_EE) {
        int rem = tid, i = 0, span = N_EL - 1;
        while (rem >= span) { rem -= span; span--; i++; }
        s_pi[tid] = i; s_pj[tid] = i + 1 + rem;
    }
    for (int idx = tid; idx < ROWS * 48; idx += THREADS) {
        int row = idx / 48, c = idx % 48;
        s_rs[row * 49 + c] = rs[(size_t)(b0 + row) * 48 + c];
    }
    __syncthreads();

    // ---- producer mappings ----
    const int rowA = tid >> 1;                  // A: row
    const int prA  = tid & 1;                   // A: which pair of the chunk
    const int swA  = rowA & 7;
    const float* myr = s_rs + rowA * 49;
    const int kB = tid >> 3;                    // B: k row (0..63)
    const int gB = tid & 7;                     // B: col16 group
    const uint32_t colB = (uint32_t)((gB ^ (kB & 7)) << 4);

    // A producer: 1 dist + 8 ex2 + 2x STS.128 per group (4 groups)
    auto produceA = [&](int chunk, uint32_t bb) {
        int p = chunk * 2 + prA;
        float dx, dy, dz;
        if (p < N_EN) {
            int e = p >> 2, a = p & 3;
            dx = myr[e * 3 + 0] - s_coord[a * 3 + 0];
            dy = myr[e * 3 + 1] - s_coord[a * 3 + 1];
            dz = myr[e * 3 + 2] - s_coord[a * 3 + 2];
        } else {
            int q = p - N_EN;
            int ii = s_pi[q], jj = s_pj[q];
            dx = myr[ii * 3 + 0] - myr[jj * 3 + 0];
            dy = myr[ii * 3 + 1] - myr[jj * 3 + 1];
            dz = myr[ii * 3 + 2] - myr[jj * 3 + 2];
        }
        float d = sqrtf(dx * dx + dy * dy + dz * dz);

        char* arow = smem + bb + A_Ho + rowA * 128;
        #pragma unroll
        for (int g4 = 0; g4 < 4; ++g4) {
            int g  = prA * 4 + g4;
            int fb = g4 * 8;
            float v[8];
            #pragma unroll
            for (int j = 0; j < 8; ++j) {
                float4 cc = s_abc[fb + j];
                v[j] = ex2(fmaf(fmaf(d, cc.x, cc.y), d, cc.z));
            }
            uint32_t hp[4], lp[4];
            #pragma unroll
            for (int t = 0; t < 4; ++t) pack_hilo(v[2 * t], v[2 * t + 1], hp[t], lp[t]);
            uint32_t col = (uint32_t)((g ^ swA) << 4);
            *(uint4*)(arow + col) = make_uint4(hp[0], hp[1], hp[2], hp[3]);
            *(uint4*)(arow + (A_Lo - A_Ho) + col) = make_uint4(lp[0], lp[1], lp[2], lp[3]);
        }
    };
    // B producer: 8 W values -> 1 hi + 1 lo STS.128
    auto produceB = [&](uint32_t bb, float4 w0, float4 w1) {
        float vv[8] = { w0.x, w0.y, w0.z, w0.w, w1.x, w1.y, w1.z, w1.w };
        uint32_t hp[4], lp[4];
        #pragma unroll
        for (int t = 0; t < 4; ++t) pack_hilo(vv[2 * t], vv[2 * t + 1], hp[t], lp[t]);
        char* brow = smem + bb + B_Ho + kB * 128;
        *(uint4*)(brow + colB) = make_uint4(hp[0], hp[1], hp[2], hp[3]);
        *(uint4*)(brow + (B_Lo - B_Ho) + colB) = make_uint4(lp[0], lp[1], lp[2], lp[3]);
    };

    // ldmatrix per-lane constants
    const int sw_l = lane & 7;
    const int hi4  = lane >> 4;
    const uint32_t arow_l = (uint32_t)((warp * 16 + (lane & 15)) * 128);
    const uint32_t brow_l = (uint32_t)((lane & 15) * 128);

    float acc[8][4];
    #pragma unroll
    for (int nt = 0; nt < 8; ++nt)
        #pragma unroll
        for (int q = 0; q < 4; ++q) acc[nt][q] = 0.0f;

    // ---- prologue: produce chunk 0 into buf0 ----
    {
        const float4* wrow = (const float4*)(W1 + (size_t)kB * HIDDEN + gB * 8);
        float4 w0 = wrow[0], w1 = wrow[1];
        produceA(0, 0);
        produceB(0, w0, w1);
    }
    __syncthreads();

    // ---- mainloop: one barrier per chunk, produce next while MMA current ----
    for (int chunk = 0; chunk < NCHUNK; ++chunk) {
        const uint32_t bbc = (uint32_t)(chunk & 1) * BUFSZ;
        const uint32_t bbn = bbc ^ BUFSZ;

        if (chunk + 1 < NCHUNK) {
            const float4* wrow = (const float4*)(W1
                + ((size_t)(chunk + 1) * CK + kB) * HIDDEN + gB * 8);
            float4 w0 = wrow[0], w1 = wrow[1];
            produceA(chunk + 1, bbn);
            produceB(bbn, w0, w1);
        }

        // ---- MMA on current buffer: warp owns 16 rows x 64 cols ----
        const uint32_t abase = sbase + bbc + A_Ho + arow_l;
        const uint32_t bbase = sbase + bbc + B_Ho + brow_l;
        #pragma unroll
        for (int ks = 0; ks < 4; ++ks) {
            uint32_t ac = (uint32_t)(((2 * ks + hi4) ^ sw_l) << 4);
            uint32_t ah[4], al[4];
            ldsm4(ah, abase + ac);
            ldsm4(al, abase + (A_Lo - A_Ho) + ac);
            #pragma unroll
            for (int j = 0; j < 4; ++j) {
                uint32_t bc = (uint32_t)(((2 * j + hi4) ^ sw_l) << 4);
                uint32_t bh4[4], bl4[4];
                ldsm4t(bh4, bbase + ks * 2048 + bc);
                ldsm4t(bl4, bbase + (B_Lo - B_Ho) + ks * 2048 + bc);
                #pragma unroll
                for (int ht = 0; ht < 2; ++ht) {
                    mma16816(acc[2 * j + ht], ah, &bh4[2 * ht]);
                    mma16816(acc[2 * j + ht], al, &bh4[2 * ht]);
                    mma16816(acc[2 * j + ht], ah, &bl4[2 * ht]);
                }
            }
        }
        __syncthreads();
    }

    // ---- stage W2 (overlay buf1) + epilogue ssp(acc+b1) -> s_h (overlay buf0) ----
    {
        const float4* wg = (const float4*)W2;
        float4* ws = (float4*)s_w2;
        #pragma unroll
        for (int i = 0; i < 2; ++i) ws[tid + i * THREADS] = wg[tid + i * THREADS];
    }
    {
        int r0 = warp * 16 + (lane >> 2);
        #pragma unroll
        for (int nt = 0; nt < 8; ++nt) {
            int c0 = nt * 8 + (lane & 3) * 2;
            s_h[r0 * 66 + c0]           = sspf(acc[nt][0] + s_b1[c0]);
            s_h[r0 * 66 + c0 + 1]       = sspf(acc[nt][1] + s_b1[c0 + 1]);
            s_h[(r0 + 8) * 66 + c0]     = sspf(acc[nt][2] + s_b1[c0]);
            s_h[(r0 + 8) * 66 + c0 + 1] = sspf(acc[nt][3] + s_b1[c0 + 1]);
        }
    }
    __syncthreads();

    // ---- layer 2/3: 2 threads per row (32 cols each) ----
    {
        const int r  = tid >> 1;
        const int hc = (tid & 1) * 32;
        float a2[32];
        #pragma unroll
        for (int c = 0; c < 32; ++c) a2[c] = 0.0f;
        const float* hrow = s_h + r * 66;
        #pragma unroll 2
        for (int k = 0; k < HIDDEN; ++k) {
            float a = hrow[k];
            const float4* w4 = (const float4*)(s_w2 + k * HIDDEN + hc);
            #pragma unroll
            for (int j = 0; j < 8; ++j) {
                float4 w = w4[j];
                a2[4 * j + 0] += a * w.x;
                a2[4 * j + 1] += a * w.y;
                a2[4 * j + 2] += a * w.z;
                a2[4 * j + 3] += a * w.w;
            }
        }
        float partial = 0.0f;
        #pragma unroll
        for (int c = 0; c < 32; ++c)
            partial += sspf(a2[c] + s_b2[hc + c]) * s_w3[hc + c];
        float other = __shfl_xor_sync(0xffffffffu, partial, 1);
        if ((tid & 1) == 0) {
            float ys = partial + other + s_b3[0];
            const float* rr = s_rs + r * 49;
            float S = 0.0f;
            #pragma unroll 4
            for (int e = 0; e < N_EL; ++e) {
                float ex_ = rr[e * 3 + 0], ey = rr[e * 3 + 1], ez = rr[e * 3 + 2];
                #pragma unroll
                for (int a = 0; a < N_NUC; ++a) {
                    float dx = ex_ - s_coord[a * 3 + 0];
                    float dy = ey - s_coord[a * 3 + 1];
                    float dz = ez - s_coord[a * 3 + 2];
                    float dd = sqrtf(dx * dx + dy * dy + dz * dz);
                    S += (s_chg[a] * dd + dd * dd) / (1.0f + dd);
                }
            }
            out[b0 + r] = expf(ys) * expf(-S);
        }
    }
}

extern "C" void kernel_launch(void* const* d_in, const int* in_sizes, int n_in,
                              void* d_out, int out_size)
{
    const float* rs      = (const float*)d_in[0];
    const float* coords  = (const float*)d_in[1];
    const float* charges = (const float*)d_in[2];
    const float* W1      = (const float*)d_in[3];
    const float* b1      = (const float*)d_in[4];
    const float* W2      = (const float*)d_in[5];
    const float* b2      = (const float*)d_in[6];
    const float* W3      = (const float*)d_in[7];
    const float* b3      = (const float*)d_in[8];
    float* out = (float*)d_out;

    int batch = in_sizes[0] / (N_EL * 3);
    int grid  = batch / ROWS;

    cudaFuncSetAttribute(wfnet_kernel,
                         cudaFuncAttributeMaxDynamicSharedMemorySize, SMEM_BYTES);
    wfnet_kernel<<<grid, THREADS, SMEM_BYTES>>>(rs, coords, charges,
                                                W1, b1, W2, b2, W3, b3, out);
}

// round 13
// speedup vs baseline: 1.0167x; 1.0167x over previous
#include <cuda_runtime.h>
#include <cuda_bf16.h>
#include <math.h>
#include <stdint.h>

#define N_EL    16
#define N_NUC   4
#define N_FEATS 32
#define N_EN    64
#define N_EE    120
#define N_PAIRS 184
#define HIDDEN  64
#define ROWS    256
#define THREADS 512
#define CK      64
#define NCHUNK  92

// ---- SMEM layout (bytes) ----
// Each buffer: A_H 256x128, A_L 256x128, B_H 64x128, B_L 64x128 = 81920
#define BUFSZ   81920
#define A_Ho    0
#define A_Lo    32768
#define B_Ho    65536
#define B_Lo    73728
#define OFF_RS  163840             // 256*49*4 = 50176
#define OFF_W2  81920              // overlay on buf1 after mainloop (16384)
#define OFF_H   0                  // overlay on buf0 after mainloop (256*66*4)
#define OFF_ABC   214016
#define OFF_COORD 214528
#define OFF_CHG   214576
#define OFF_B1    214592
#define OFF_B2    214848
#define OFF_W3    215104
#define OFF_B3    215360
#define OFF_PI    215376
#define OFF_PJ    215856
#define SMEM_BYTES 216448

#define LOG2E 1.4426950408889634f

__device__ __forceinline__ float sspf(float x) {
    return fmaxf(x, 0.0f) + log1pf(expf(-fabsf(x))) - 0.69314718055994531f;
}
__device__ __forceinline__ float ex2(float x) {
    float r; asm("ex2.approx.ftz.f32 %0, %1;" : "=f"(r) : "f"(x)); return r;
}
__device__ __forceinline__ uint32_t smem_u32(const void* p) {
    uint32_t a;
    asm("{ .reg .u64 t; cvta.to.shared.u64 t, %1; cvt.u32.u64 %0, t; }"
        : "=r"(a) : "l"(p));
    return a;
}
__device__ __forceinline__ void ldsm4(uint32_t* r, uint32_t a) {
    asm volatile("ldmatrix.sync.aligned.m8n8.x4.shared.b16 {%0,%1,%2,%3}, [%4];"
        : "=r"(r[0]), "=r"(r[1]), "=r"(r[2]), "=r"(r[3]) : "r"(a));
}
__device__ __forceinline__ void ldsm4t(uint32_t* r, uint32_t a) {
    asm volatile("ldmatrix.sync.aligned.m8n8.x4.trans.shared.b16 {%0,%1,%2,%3}, [%4];"
        : "=r"(r[0]), "=r"(r[1]), "=r"(r[2]), "=r"(r[3]) : "r"(a));
}
__device__ __forceinline__ void mma16816(float* c, const uint32_t* a, const uint32_t* b) {
    asm volatile("mma.sync.aligned.m16n8k16.row.col.f32.bf16.bf16.f32 "
        "{%0,%1,%2,%3}, {%4,%5,%6,%7}, {%8,%9}, {%0,%1,%2,%3};"
        : "+f"(c[0]), "+f"(c[1]), "+f"(c[2]), "+f"(c[3])
        : "r"(a[0]), "r"(a[1]), "r"(a[2]), "r"(a[3]), "r"(b[0]), "r"(b[1]));
}
// hi = bf16-truncate of (a,b) packed; lo = rn-bf16 of residuals packed
__device__ __forceinline__ void pack_hilo(float a, float b, uint32_t& hp, uint32_t& lp) {
    uint32_t ua = __float_as_uint(a), ub = __float_as_uint(b);
    hp = __byte_perm(ua, ub, 0x7632);
    float ha = __uint_as_float(ua & 0xffff0000u);
    float hb = __uint_as_float(ub & 0xffff0000u);
    __nv_bfloat162 l2 = __floats2bfloat162_rn(a - ha, b - hb);
    lp = *reinterpret_cast<uint32_t*>(&l2);
}

__global__ __launch_bounds__(THREADS, 1)
void wfnet_kernel(const float* __restrict__ rs,
                  const float* __restrict__ coords,
                  const float* __restrict__ charges,
                  const float* __restrict__ W1,
                  const float* __restrict__ b1,
                  const float* __restrict__ W2,
                  const float* __restrict__ b2,
                  const float* __restrict__ W3,
                  const float* __restrict__ b3,
                  float* __restrict__ out)
{
    extern __shared__ char smem[];
    const uint32_t sbase = smem_u32(smem);

    float4* s_abc  = (float4*)(smem + OFF_ABC);
    float* s_coord = (float*)(smem + OFF_COORD);
    float* s_chg   = (float*)(smem + OFF_CHG);
    float* s_b1    = (float*)(smem + OFF_B1);
    float* s_b2    = (float*)(smem + OFF_B2);
    float* s_w3    = (float*)(smem + OFF_W3);
    float* s_b3    = (float*)(smem + OFF_B3);
    int*   s_pi    = (int*)  (smem + OFF_PI);
    int*   s_pj    = (int*)  (smem + OFF_PJ);
    float* s_rs    = (float*)(smem + OFF_RS);
    float* s_w2    = (float*)(smem + OFF_W2);
    float* s_h     = (float*)(smem + OFF_H);

    const int tid  = threadIdx.x;
    const int b0   = blockIdx.x * ROWS;
    const int lane = tid & 31;
    const int warp = tid >> 5;
    const int wr   = warp >> 1;          // row group: rows wr*32..+32
    const int jc   = warp & 1;           // col half:  cols jc*32..+32

    // ---- setup ----
    if (tid < N_FEATS) {
        float q   = (float)tid / 31.0f;
        float mu  = 10.0f * q * q;
        float sig = (1.0f + 10.0f * q) * (1.0f / 7.0f);
        float a   = -LOG2E / (sig * sig);
        s_abc[tid] = make_float4(a, -2.0f * mu * a, a * mu * mu, 0.0f);
    }
    if (tid < 12) s_coord[tid] = coords[tid];
    if (tid < 4)  s_chg[tid]   = charges[tid];
    if (tid < HIDDEN) { s_b1[tid] = b1[tid]; s_b2[tid] = b2[tid]; s_w3[tid] = W3[tid]; }
    if (tid == 0) s_b3[0] = b3[0];
    if (tid < N_EE) {
        int rem = tid, i = 0, span = N_EL - 1;
        while (rem >= span) { rem -= span; span--; i++; }
        s_pi[tid] = i; s_pj[tid] = i + 1 + rem;
    }
    for (int idx = tid; idx < ROWS * 48; idx += THREADS) {
        int row = idx / 48, c = idx % 48;
        s_rs[row * 49 + c] = rs[(size_t)(b0 + row) * 48 + c];
    }
    __syncthreads();

    // ---- producer mappings ----
    const int rowA = tid >> 1;                  // A: row
    const int prA  = tid & 1;                   // A: which pair of the chunk
    const int swA  = rowA & 7;
    const float* myr = s_rs + rowA * 49;
    const int kB = tid >> 3;                    // B: k row (0..63)
    const int gB = tid & 7;                     // B: col16 group
    const uint32_t colB = (uint32_t)((gB ^ (kB & 7)) << 4);

    // A producer: 1 dist + 8 ex2 + 2x STS.128 per group (4 groups)
    auto produceA = [&](int chunk, uint32_t bb) {
        int p = chunk * 2 + prA;
        float dx, dy, dz;
        if (p < N_EN) {
            int e = p >> 2, a = p & 3;
            dx = myr[e * 3 + 0] - s_coord[a * 3 + 0];
            dy = myr[e * 3 + 1] - s_coord[a * 3 + 1];
            dz = myr[e * 3 + 2] - s_coord[a * 3 + 2];
        } else {
            int q = p - N_EN;
            int ii = s_pi[q], jj = s_pj[q];
            dx = myr[ii * 3 + 0] - myr[jj * 3 + 0];
            dy = myr[ii * 3 + 1] - myr[jj * 3 + 1];
            dz = myr[ii * 3 + 2] - myr[jj * 3 + 2];
        }
        float d = sqrtf(dx * dx + dy * dy + dz * dz);

        char* arow = smem + bb + A_Ho + rowA * 128;
        #pragma unroll
        for (int g4 = 0; g4 < 4; ++g4) {
            int g  = prA * 4 + g4;
            int fb = g4 * 8;
            float v[8];
            #pragma unroll
            for (int j = 0; j < 8; ++j) {
                float4 cc = s_abc[fb + j];
                v[j] = ex2(fmaf(fmaf(d, cc.x, cc.y), d, cc.z));
            }
            uint32_t hp[4], lp[4];
            #pragma unroll
            for (int t = 0; t < 4; ++t) pack_hilo(v[2 * t], v[2 * t + 1], hp[t], lp[t]);
            uint32_t col = (uint32_t)((g ^ swA) << 4);
            *(uint4*)(arow + col) = make_uint4(hp[0], hp[1], hp[2], hp[3]);
            *(uint4*)(arow + (A_Lo - A_Ho) + col) = make_uint4(lp[0], lp[1], lp[2], lp[3]);
        }
    };
    // B producer: 8 W values -> 1 hi + 1 lo STS.128
    auto produceB = [&](uint32_t bb, float4 w0, float4 w1) {
        float vv[8] = { w0.x, w0.y, w0.z, w0.w, w1.x, w1.y, w1.z, w1.w };
        uint32_t hp[4], lp[4];
        #pragma unroll
        for (int t = 0; t < 4; ++t) pack_hilo(vv[2 * t], vv[2 * t + 1], hp[t], lp[t]);
        char* brow = smem + bb + B_Ho + kB * 128;
        *(uint4*)(brow + colB) = make_uint4(hp[0], hp[1], hp[2], hp[3]);
        *(uint4*)(brow + (B_Lo - B_Ho) + colB) = make_uint4(lp[0], lp[1], lp[2], lp[3]);
    };

    // ldmatrix per-lane constants
    const int sw_l = lane & 7;
    const int hi4  = lane >> 4;
    const uint32_t arow_l = (uint32_t)((wr * 32 + (lane & 15)) * 128);
    const uint32_t brow_l = (uint32_t)((lane & 15) * 128);

    float acc[2][4][4];
    #pragma unroll
    for (int mt = 0; mt < 2; ++mt)
        #pragma unroll
        for (int nt = 0; nt < 4; ++nt)
            #pragma unroll
            for (int q = 0; q < 4; ++q) acc[mt][nt][q] = 0.0f;

    // ---- prologue: produce chunk 0 into buf0 ----
    {
        const float4* wrow = (const float4*)(W1 + (size_t)kB * HIDDEN + gB * 8);
        float4 w0 = wrow[0], w1 = wrow[1];
        produceA(0, 0);
        produceB(0, w0, w1);
    }
    __syncthreads();

    // ---- mainloop: one barrier per chunk, produce next while MMA current ----
    for (int chunk = 0; chunk < NCHUNK; ++chunk) {
        const uint32_t bbc = (uint32_t)(chunk & 1) * BUFSZ;
        const uint32_t bbn = bbc ^ BUFSZ;

        if (chunk + 1 < NCHUNK) {
            const float4* wrow = (const float4*)(W1
                + ((size_t)(chunk + 1) * CK + kB) * HIDDEN + gB * 8);
            float4 w0 = wrow[0], w1 = wrow[1];
            produceA(chunk + 1, bbn);
            produceB(bbn, w0, w1);
        }

        // ---- MMA on current buffer: warp owns 32 rows x 32 cols ----
        const uint32_t abase = sbase + bbc + A_Ho + arow_l;
        const uint32_t bbase = sbase + bbc + B_Ho + brow_l;
        #pragma unroll
        for (int ks = 0; ks < 4; ++ks) {
            uint32_t ac = (uint32_t)(((2 * ks + hi4) ^ sw_l) << 4);
            uint32_t ah[2][4], al[2][4];
            ldsm4(ah[0], abase + ac);
            ldsm4(ah[1], abase + 2048 + ac);                    // +16 rows
            ldsm4(al[0], abase + (A_Lo - A_Ho) + ac);
            ldsm4(al[1], abase + (A_Lo - A_Ho) + 2048 + ac);
            #pragma unroll
            for (int j = 0; j < 2; ++j) {
                uint32_t bc = (uint32_t)(((2 * (jc * 2 + j) + hi4) ^ sw_l) << 4);
                uint32_t bh4[4], bl4[4];
                ldsm4t(bh4, bbase + ks * 2048 + bc);
                ldsm4t(bl4, bbase + (B_Lo - B_Ho) + ks * 2048 + bc);
                #pragma unroll
                for (int ht = 0; ht < 2; ++ht) {
                    #pragma unroll
                    for (int mt = 0; mt < 2; ++mt) {
                        mma16816(acc[mt][2 * j + ht], ah[mt], &bh4[2 * ht]);
                        mma16816(acc[mt][2 * j + ht], al[mt], &bh4[2 * ht]);
                        mma16816(acc[mt][2 * j + ht], ah[mt], &bl4[2 * ht]);
                    }
                }
            }
        }
        __syncthreads();
    }

    // ---- stage W2 (overlay buf1) + epilogue ssp(acc+b1) -> s_h (overlay buf0) ----
    {
        const float4* wg = (const float4*)W2;
        float4* ws = (float4*)s_w2;
        #pragma unroll
        for (int i = 0; i < 2; ++i) ws[tid + i * THREADS] = wg[tid + i * THREADS];
    }
    #pragma unroll
    for (int mt = 0; mt < 2; ++mt) {
        int r0 = wr * 32 + mt * 16 + (lane >> 2);
        #pragma unroll
        for (int nt = 0; nt < 4; ++nt) {
            int c0 = jc * 32 + (nt >> 1) * 16 + (nt & 1) * 8 + (lane & 3) * 2;
            s_h[r0 * 66 + c0]           = sspf(acc[mt][nt][0] + s_b1[c0]);
            s_h[r0 * 66 + c0 + 1]       = sspf(acc[mt][nt][1] + s_b1[c0 + 1]);
            s_h[(r0 + 8) * 66 + c0]     = sspf(acc[mt][nt][2] + s_b1[c0]);
            s_h[(r0 + 8) * 66 + c0 + 1] = sspf(acc[mt][nt][3] + s_b1[c0 + 1]);
        }
    }
    __syncthreads();

    // ---- layer 2/3: 2 threads per row (32 cols each) ----
    {
        const int r  = tid >> 1;
        const int hc = (tid & 1) * 32;
        float a2[32];
        #pragma unroll
        for (int c = 0; c < 32; ++c) a2[c] = 0.0f;
        const float* hrow = s_h + r * 66;
        #pragma unroll 2
        for (int k = 0; k < HIDDEN; ++k) {
            float a = hrow[k];
            const float4* w4 = (const float4*)(s_w2 + k * HIDDEN + hc);
            #pragma unroll
            for (int j = 0; j < 8; ++j) {
                float4 w = w4[j];
                a2[4 * j + 0] += a * w.x;
                a2[4 * j + 1] += a * w.y;
                a2[4 * j + 2] += a * w.z;
                a2[4 * j + 3] += a * w.w;
            }
        }
        float partial = 0.0f;
        #pragma unroll
        for (int c = 0; c < 32; ++c)
            partial += sspf(a2[c] + s_b2[hc + c]) * s_w3[hc + c];
        float other = __shfl_xor_sync(0xffffffffu, partial, 1);
        if ((tid & 1) == 0) {
            float ys = partial + other + s_b3[0];
            const float* rr = s_rs + r * 49;
            float S = 0.0f;
            #pragma unroll 4
            for (int e = 0; e < N_EL; ++e) {
                float ex_ = rr[e * 3 + 0], ey = rr[e * 3 + 1], ez = rr[e * 3 + 2];
                #pragma unroll
                for (int a = 0; a < N_NUC; ++a) {
                    float dx = ex_ - s_coord[a * 3 + 0];
                    float dy = ey - s_coord[a * 3 + 1];
                    float dz = ez - s_coord[a * 3 + 2];
                    float dd = sqrtf(dx * dx + dy * dy + dz * dz);
                    S += (s_chg[a] * dd + dd * dd) / (1.0f + dd);
                }
            }
            out[b0 + r] = expf(ys) * expf(-S);
        }
    }
}

extern "C" void kernel_launch(void* const* d_in, const int* in_sizes, int n_in,
                              void* d_out, int out_size)
{
    const float* rs      = (const float*)d_in[0];
    const float* coords  = (const float*)d_in[1];
    const float* charges = (const float*)d_in[2];
    const float* W1      = (const float*)d_in[3];
    const float* b1      = (const float*)d_in[4];
    const float* W2      = (const float*)d_in[5];
    const float* b2      = (const float*)d_in[6];
    const float* W3      = (const float*)d_in[7];
    const float* b3      = (const float*)d_in[8];
    float* out = (float*)d_out;

    int batch = in_sizes[0] / (N_EL * 3);
    int grid  = batch / ROWS;

    cudaFuncSetAttribute(wfnet_kernel,
                         cudaFuncAttributeMaxDynamicSharedMemorySize, SMEM_BYTES);
    wfnet_kernel<<<grid, THREADS, SMEM_BYTES>>>(rs, coords, charges,
                                                W1, b1, W2, b2, W3, b3, out);
}

// round 14
// speedup vs baseline: 1.2184x; 1.1984x over previous
#include <cuda_runtime.h>
#include <cuda_bf16.h>
#include <math.h>
#include <stdint.h>

#define N_EL    16
#define N_NUC   4
#define N_FEATS 32
#define N_EN    64
#define N_EE    120
#define N_PAIRS 184
#define HIDDEN  64
#define ROWS    256
#define THREADS 512
#define CK      64
#define NCHUNK  92

// ---- SMEM layout (bytes) ----
// Each buffer: A_H 256x128, A_L 256x128, B_H 64x128 = 73728
#define BUFSZ   73728
#define A_Ho    0
#define A_Lo    32768
#define B_Ho    65536
#define OFF_RS  147456             // 256*49*4 = 50176
#define OFF_W2  73728              // overlay on buf1 after mainloop (16384)
#define OFF_H   0                  // overlay on buf0 after mainloop (256*66*4)
#define OFF_ABC   197632
#define OFF_COORD 198144
#define OFF_CHG   198192
#define OFF_B1    198208
#define OFF_B2    198464
#define OFF_W3    198720
#define OFF_B3    198976
#define OFF_PI    198992
#define OFF_PJ    199472
#define SMEM_BYTES 199952

#define LOG2E 1.4426950408889634f

__device__ __forceinline__ float sspf(float x) {
    return fmaxf(x, 0.0f) + log1pf(expf(-fabsf(x))) - 0.69314718055994531f;
}
__device__ __forceinline__ float ex2(float x) {
    float r; asm("ex2.approx.ftz.f32 %0, %1;" : "=f"(r) : "f"(x)); return r;
}
__device__ __forceinline__ uint32_t smem_u32(const void* p) {
    uint32_t a;
    asm("{ .reg .u64 t; cvta.to.shared.u64 t, %1; cvt.u32.u64 %0, t; }"
        : "=r"(a) : "l"(p));
    return a;
}
__device__ __forceinline__ void ldsm4(uint32_t* r, uint32_t a) {
    asm volatile("ldmatrix.sync.aligned.m8n8.x4.shared.b16 {%0,%1,%2,%3}, [%4];"
        : "=r"(r[0]), "=r"(r[1]), "=r"(r[2]), "=r"(r[3]) : "r"(a));
}
__device__ __forceinline__ void ldsm4t(uint32_t* r, uint32_t a) {
    asm volatile("ldmatrix.sync.aligned.m8n8.x4.trans.shared.b16 {%0,%1,%2,%3}, [%4];"
        : "=r"(r[0]), "=r"(r[1]), "=r"(r[2]), "=r"(r[3]) : "r"(a));
}
__device__ __forceinline__ void mma16816(float* c, const uint32_t* a, const uint32_t* b) {
    asm volatile("mma.sync.aligned.m16n8k16.row.col.f32.bf16.bf16.f32 "
        "{%0,%1,%2,%3}, {%4,%5,%6,%7}, {%8,%9}, {%0,%1,%2,%3};"
        : "+f"(c[0]), "+f"(c[1]), "+f"(c[2]), "+f"(c[3])
        : "r"(a[0]), "r"(a[1]), "r"(a[2]), "r"(a[3]), "r"(b[0]), "r"(b[1]));
}
// hi = bf16-truncate of (a,b) packed; lo = rn-bf16 of residuals packed
__device__ __forceinline__ void pack_hilo(float a, float b, uint32_t& hp, uint32_t& lp) {
    uint32_t ua = __float_as_uint(a), ub = __float_as_uint(b);
    hp = __byte_perm(ua, ub, 0x7632);
    float ha = __uint_as_float(ua & 0xffff0000u);
    float hb = __uint_as_float(ub & 0xffff0000u);
    __nv_bfloat162 l2 = __floats2bfloat162_rn(a - ha, b - hb);
    lp = *reinterpret_cast<uint32_t*>(&l2);
}
// rn-bf16 pair pack (for B: single term, round to nearest)
__device__ __forceinline__ uint32_t pack_rn(float a, float b) {
    __nv_bfloat162 h2 = __floats2bfloat162_rn(a, b);
    return *reinterpret_cast<uint32_t*>(&h2);
}

__global__ __launch_bounds__(THREADS, 1)
void wfnet_kernel(const float* __restrict__ rs,
                  const float* __restrict__ coords,
                  const float* __restrict__ charges,
                  const float* __restrict__ W1,
                  const float* __restrict__ b1,
                  const float* __restrict__ W2,
                  const float* __restrict__ b2,
                  const float* __restrict__ W3,
                  const float* __restrict__ b3,
                  float* __restrict__ out)
{
    extern __shared__ char smem[];
    const uint32_t sbase = smem_u32(smem);

    float4* s_abc  = (float4*)(smem + OFF_ABC);
    float* s_coord = (float*)(smem + OFF_COORD);
    float* s_chg   = (float*)(smem + OFF_CHG);
    float* s_b1    = (float*)(smem + OFF_B1);
    float* s_b2    = (float*)(smem + OFF_B2);
    float* s_w3    = (float*)(smem + OFF_W3);
    float* s_b3    = (float*)(smem + OFF_B3);
    int*   s_pi    = (int*)  (smem + OFF_PI);
    int*   s_pj    = (int*)  (smem + OFF_PJ);
    float* s_rs    = (float*)(smem + OFF_RS);
    float* s_w2    = (float*)(smem + OFF_W2);
    float* s_h     = (float*)(smem + OFF_H);

    const int tid  = threadIdx.x;
    const int b0   = blockIdx.x * ROWS;
    const int lane = tid & 31;
    const int warp = tid >> 5;
    const int wr   = warp >> 1;          // row group: rows wr*32..+32
    const int jc   = warp & 1;           // col half:  cols jc*32..+32

    // ---- setup ----
    if (tid < N_FEATS) {
        float q   = (float)tid / 31.0f;
        float mu  = 10.0f * q * q;
        float sig = (1.0f + 10.0f * q) * (1.0f / 7.0f);
        float a   = -LOG2E / (sig * sig);
        s_abc[tid] = make_float4(a, -2.0f * mu * a, a * mu * mu, 0.0f);
    }
    if (tid < 12) s_coord[tid] = coords[tid];
    if (tid < 4)  s_chg[tid]   = charges[tid];
    if (tid < HIDDEN) { s_b1[tid] = b1[tid]; s_b2[tid] = b2[tid]; s_w3[tid] = W3[tid]; }
    if (tid == 0) s_b3[0] = b3[0];
    if (tid < N_EE) {
        int rem = tid, i = 0, span = N_EL - 1;
        while (rem >= span) { rem -= span; span--; i++; }
        s_pi[tid] = i; s_pj[tid] = i + 1 + rem;
    }
    for (int idx = tid; idx < ROWS * 48; idx += THREADS) {
        int row = idx / 48, c = idx % 48;
        s_rs[row * 49 + c] = rs[(size_t)(b0 + row) * 48 + c];
    }
    __syncthreads();

    // ---- producer mappings ----
    const int rowA = tid >> 1;                  // A: row
    const int prA  = tid & 1;                   // A: which pair of the chunk
    const int swA  = rowA & 7;
    const float* myr = s_rs + rowA * 49;
    const int kB = tid >> 3;                    // B: k row (0..63)
    const int gB = tid & 7;                     // B: col16 group
    const uint32_t colB = (uint32_t)((gB ^ (kB & 7)) << 4);

    // A producer: 1 dist + 8 ex2 + 2x STS.128 per group (4 groups)
    auto produceA = [&](int chunk, uint32_t bb) {
        int p = chunk * 2 + prA;
        float dx, dy, dz;
        if (p < N_EN) {
            int e = p >> 2, a = p & 3;
            dx = myr[e * 3 + 0] - s_coord[a * 3 + 0];
            dy = myr[e * 3 + 1] - s_coord[a * 3 + 1];
            dz = myr[e * 3 + 2] - s_coord[a * 3 + 2];
        } else {
            int q = p - N_EN;
            int ii = s_pi[q], jj = s_pj[q];
            dx = myr[ii * 3 + 0] - myr[jj * 3 + 0];
            dy = myr[ii * 3 + 1] - myr[jj * 3 + 1];
            dz = myr[ii * 3 + 2] - myr[jj * 3 + 2];
        }
        float d = sqrtf(dx * dx + dy * dy + dz * dz);

        char* arow = smem + bb + A_Ho + rowA * 128;
        #pragma unroll
        for (int g4 = 0; g4 < 4; ++g4) {
            int g  = prA * 4 + g4;
            int fb = g4 * 8;
            float v[8];
            #pragma unroll
            for (int j = 0; j < 8; ++j) {
                float4 cc = s_abc[fb + j];
                v[j] = ex2(fmaf(fmaf(d, cc.x, cc.y), d, cc.z));
            }
            uint32_t hp[4], lp[4];
            #pragma unroll
            for (int t = 0; t < 4; ++t) pack_hilo(v[2 * t], v[2 * t + 1], hp[t], lp[t]);
            uint32_t col = (uint32_t)((g ^ swA) << 4);
            *(uint4*)(arow + col) = make_uint4(hp[0], hp[1], hp[2], hp[3]);
            *(uint4*)(arow + (A_Lo - A_Ho) + col) = make_uint4(lp[0], lp[1], lp[2], lp[3]);
        }
    };
    // B producer: 8 W values -> 1 STS.128 (hi only, round-to-nearest)
    auto produceB = [&](uint32_t bb, float4 w0, float4 w1) {
        uint32_t hp[4];
        hp[0] = pack_rn(w0.x, w0.y);
        hp[1] = pack_rn(w0.z, w0.w);
        hp[2] = pack_rn(w1.x, w1.y);
        hp[3] = pack_rn(w1.z, w1.w);
        char* brow = smem + bb + B_Ho + kB * 128;
        *(uint4*)(brow + colB) = make_uint4(hp[0], hp[1], hp[2], hp[3]);
    };

    // ldmatrix per-lane constants
    const int sw_l = lane & 7;
    const int hi4  = lane >> 4;
    const uint32_t arow_l = (uint32_t)((wr * 32 + (lane & 15)) * 128);
    const uint32_t brow_l = (uint32_t)((lane & 15) * 128);

    float acc[2][4][4];
    #pragma unroll
    for (int mt = 0; mt < 2; ++mt)
        #pragma unroll
        for (int nt = 0; nt < 4; ++nt)
            #pragma unroll
            for (int q = 0; q < 4; ++q) acc[mt][nt][q] = 0.0f;

    // ---- prologue: produce chunk 0 into buf0 ----
    {
        const float4* wrow = (const float4*)(W1 + (size_t)kB * HIDDEN + gB * 8);
        float4 w0 = wrow[0], w1 = wrow[1];
        produceA(0, 0);
        produceB(0, w0, w1);
    }
    __syncthreads();

    // ---- mainloop: one barrier per chunk, produce next while MMA current ----
    for (int chunk = 0; chunk < NCHUNK; ++chunk) {
        const uint32_t bbc = (uint32_t)(chunk & 1) * BUFSZ;
        const uint32_t bbn = bbc ^ BUFSZ;

        if (chunk + 1 < NCHUNK) {
            const float4* wrow = (const float4*)(W1
                + ((size_t)(chunk + 1) * CK + kB) * HIDDEN + gB * 8);
            float4 w0 = wrow[0], w1 = wrow[1];
            produceA(chunk + 1, bbn);
            produceB(bbn, w0, w1);
        }

        // ---- MMA on current buffer: warp owns 32 rows x 32 cols, 2 terms ----
        const uint32_t abase = sbase + bbc + A_Ho + arow_l;
        const uint32_t bbase = sbase + bbc + B_Ho + brow_l;
        #pragma unroll
        for (int ks = 0; ks < 4; ++ks) {
            uint32_t ac = (uint32_t)(((2 * ks + hi4) ^ sw_l) << 4);
            uint32_t ah[2][4], al[2][4];
            ldsm4(ah[0], abase + ac);
            ldsm4(ah[1], abase + 2048 + ac);                    // +16 rows
            ldsm4(al[0], abase + (A_Lo - A_Ho) + ac);
            ldsm4(al[1], abase + (A_Lo - A_Ho) + 2048 + ac);
            uint32_t bh[2][4];
            #pragma unroll
            for (int j = 0; j < 2; ++j) {
                uint32_t bc = (uint32_t)(((2 * (jc * 2 + j) + hi4) ^ sw_l) << 4);
                ldsm4t(bh[j], bbase + ks * 2048 + bc);
            }
            // pass 1: hi term, 8 independent MMAs (distinct accumulators)
            #pragma unroll
            for (int j = 0; j < 2; ++j)
                #pragma unroll
                for (int ht = 0; ht < 2; ++ht)
                    #pragma unroll
                    for (int mt = 0; mt < 2; ++mt)
                        mma16816(acc[mt][2 * j + ht], ah[mt], &bh[j][2 * ht]);
            // pass 2: lo-A correction term
            #pragma unroll
            for (int j = 0; j < 2; ++j)
                #pragma unroll
                for (int ht = 0; ht < 2; ++ht)
                    #pragma unroll
                    for (int mt = 0; mt < 2; ++mt)
                        mma16816(acc[mt][2 * j + ht], al[mt], &bh[j][2 * ht]);
        }
        __syncthreads();
    }

    // ---- stage W2 (overlay buf1) + epilogue ssp(acc+b1) -> s_h (overlay buf0) ----
    {
        const float4* wg = (const float4*)W2;
        float4* ws = (float4*)s_w2;
        #pragma unroll
        for (int i = 0; i < 2; ++i) ws[tid + i * THREADS] = wg[tid + i * THREADS];
    }
    #pragma unroll
    for (int mt = 0; mt < 2; ++mt) {
        int r0 = wr * 32 + mt * 16 + (lane >> 2);
        #pragma unroll
        for (int nt = 0; nt < 4; ++nt) {
            int c0 = jc * 32 + (nt >> 1) * 16 + (nt & 1) * 8 + (lane & 3) * 2;
            s_h[r0 * 66 + c0]           = sspf(acc[mt][nt][0] + s_b1[c0]);
            s_h[r0 * 66 + c0 + 1]       = sspf(acc[mt][nt][1] + s_b1[c0 + 1]);
            s_h[(r0 + 8) * 66 + c0]     = sspf(acc[mt][nt][2] + s_b1[c0]);
            s_h[(r0 + 8) * 66 + c0 + 1] = sspf(acc[mt][nt][3] + s_b1[c0 + 1]);
        }
    }
    __syncthreads();

    // ---- layer 2/3: 2 threads per row (32 cols each) ----
    {
        const int r  = tid >> 1;
        const int hc = (tid & 1) * 32;
        float a2[32];
        #pragma unroll
        for (int c = 0; c < 32; ++c) a2[c] = 0.0f;
        const float* hrow = s_h + r * 66;
        #pragma unroll 2
        for (int k = 0; k < HIDDEN; ++k) {
            float a = hrow[k];
            const float4* w4 = (const float4*)(s_w2 + k * HIDDEN + hc);
            #pragma unroll
            for (int j = 0; j < 8; ++j) {
                float4 w = w4[j];
                a2[4 * j + 0] += a * w.x;
                a2[4 * j + 1] += a * w.y;
                a2[4 * j + 2] += a * w.z;
                a2[4 * j + 3] += a * w.w;
            }
        }
        float partial = 0.0f;
        #pragma unroll
        for (int c = 0; c < 32; ++c)
            partial += sspf(a2[c] + s_b2[hc + c]) * s_w3[hc + c];
        float other = __shfl_xor_sync(0xffffffffu, partial, 1);
        if ((tid & 1) == 0) {
            float ys = partial + other + s_b3[0];
            const float* rr = s_rs + r * 49;
            float S = 0.0f;
            #pragma unroll 4
            for (int e = 0; e < N_EL; ++e) {
                float ex_ = rr[e * 3 + 0], ey = rr[e * 3 + 1], ez = rr[e * 3 + 2];
                #pragma unroll
                for (int a = 0; a < N_NUC; ++a) {
                    float dx = ex_ - s_coord[a * 3 + 0];
                    float dy = ey - s_coord[a * 3 + 1];
                    float dz = ez - s_coord[a * 3 + 2];
                    float dd = sqrtf(dx * dx + dy * dy + dz * dz);
                    S += (s_chg[a] * dd + dd * dd) / (1.0f + dd);
                }
            }
            out[b0 + r] = expf(ys) * expf(-S);
        }
    }
}

extern "C" void kernel_launch(void* const* d_in, const int* in_sizes, int n_in,
                              void* d_out, int out_size)
{
    const float* rs      = (const float*)d_in[0];
    const float* coords  = (const float*)d_in[1];
    const float* charges = (const float*)d_in[2];
    const float* W1      = (const float*)d_in[3];
    const float* b1      = (const float*)d_in[4];
    const float* W2      = (const float*)d_in[5];
    const float* b2      = (const float*)d_in[6];
    const float* W3      = (const float*)d_in[7];
    const float* b3      = (const float*)d_in[8];
    float* out = (float*)d_out;

    int batch = in_sizes[0] / (N_EL * 3);
    int grid  = batch / ROWS;

    cudaFuncSetAttribute(wfnet_kernel,
                         cudaFuncAttributeMaxDynamicSharedMemorySize, SMEM_BYTES);
    wfnet_kernel<<<grid, THREADS, SMEM_BYTES>>>(rs, coords, charges,
                                                W1, b1, W2, b2, W3, b3, out);
}

// round 15
// speedup vs baseline: 1.6353x; 1.3421x over previous
#include <cuda_runtime.h>
#include <cuda_fp16.h>
#include <math.h>
#include <stdint.h>

#define N_EL    16
#define N_NUC   4
#define N_FEATS 32
#define N_EN    64
#define N_EE    120
#define N_PAIRS 184
#define HIDDEN  64
#define ROWS    256
#define THREADS 512
#define CK      64
#define NCHUNK  92

// ---- SMEM layout (bytes) ----
// Each buffer: A 256x128 (64 fp16/row), B 64x128 = 40960
#define BUFSZ   40960
#define A_o     0
#define B_o     32768
#define OFF_RS  81920              // 256*49*4 = 50176
#define OFF_W2  132096             // 16384
#define OFF_H   0                  // overlay on buffers after mainloop (256*66*4 = 67584)
#define OFF_ABC   148480
#define OFF_COORD 148992
#define OFF_CHG   149040
#define OFF_B1    149056
#define OFF_B2    149312
#define OFF_W3    149568
#define OFF_B3    149824
#define OFF_PI    149840
#define OFF_PJ    150320
#define SMEM_BYTES 150800

#define LOG2E 1.4426950408889634f

__device__ __forceinline__ float sspf(float x) {
    return fmaxf(x, 0.0f) + log1pf(expf(-fabsf(x))) - 0.69314718055994531f;
}
__device__ __forceinline__ float ex2(float x) {
    float r; asm("ex2.approx.ftz.f32 %0, %1;" : "=f"(r) : "f"(x)); return r;
}
__device__ __forceinline__ uint32_t smem_u32(const void* p) {
    uint32_t a;
    asm("{ .reg .u64 t; cvta.to.shared.u64 t, %1; cvt.u32.u64 %0, t; }"
        : "=r"(a) : "l"(p));
    return a;
}
__device__ __forceinline__ void ldsm4(uint32_t* r, uint32_t a) {
    asm volatile("ldmatrix.sync.aligned.m8n8.x4.shared.b16 {%0,%1,%2,%3}, [%4];"
        : "=r"(r[0]), "=r"(r[1]), "=r"(r[2]), "=r"(r[3]) : "r"(a));
}
__device__ __forceinline__ void ldsm4t(uint32_t* r, uint32_t a) {
    asm volatile("ldmatrix.sync.aligned.m8n8.x4.trans.shared.b16 {%0,%1,%2,%3}, [%4];"
        : "=r"(r[0]), "=r"(r[1]), "=r"(r[2]), "=r"(r[3]) : "r"(a));
}
__device__ __forceinline__ void mma16816(float* c, const uint32_t* a, const uint32_t* b) {
    asm volatile("mma.sync.aligned.m16n8k16.row.col.f32.f16.f16.f32 "
        "{%0,%1,%2,%3}, {%4,%5,%6,%7}, {%8,%9}, {%0,%1,%2,%3};"
        : "+f"(c[0]), "+f"(c[1]), "+f"(c[2]), "+f"(c[3])
        : "r"(a[0]), "r"(a[1]), "r"(a[2]), "r"(a[3]), "r"(b[0]), "r"(b[1]));
}
__device__ __forceinline__ uint32_t packh2(float a, float b) {
    __half2 h = __floats2half2_rn(a, b);
    return *reinterpret_cast<uint32_t*>(&h);
}

__global__ __launch_bounds__(THREADS, 1)
void wfnet_kernel(const float* __restrict__ rs,
                  const float* __restrict__ coords,
                  const float* __restrict__ charges,
                  const float* __restrict__ W1,
                  const float* __restrict__ b1,
                  const float* __restrict__ W2,
                  const float* __restrict__ b2,
                  const float* __restrict__ W3,
                  const float* __restrict__ b3,
                  float* __restrict__ out)
{
    extern __shared__ char smem[];
    const uint32_t sbase = smem_u32(smem);

    float4* s_abc  = (float4*)(smem + OFF_ABC);
    float* s_coord = (float*)(smem + OFF_COORD);
    float* s_chg   = (float*)(smem + OFF_CHG);
    float* s_b1    = (float*)(smem + OFF_B1);
    float* s_b2    = (float*)(smem + OFF_B2);
    float* s_w3    = (float*)(smem + OFF_W3);
    float* s_b3    = (float*)(smem + OFF_B3);
    int*   s_pi    = (int*)  (smem + OFF_PI);
    int*   s_pj    = (int*)  (smem + OFF_PJ);
    float* s_rs    = (float*)(smem + OFF_RS);
    float* s_w2    = (float*)(smem + OFF_W2);
    float* s_h     = (float*)(smem + OFF_H);

    const int tid  = threadIdx.x;
    const int b0   = blockIdx.x * ROWS;
    const int lane = tid & 31;
    const int warp = tid >> 5;
    const int wr   = warp >> 1;          // row group: rows wr*32..+32
    const int jc   = warp & 1;           // col half:  cols jc*32..+32

    // ---- setup ----
    if (tid < N_FEATS) {
        float q   = (float)tid / 31.0f;
        float mu  = 10.0f * q * q;
        float sig = (1.0f + 10.0f * q) * (1.0f / 7.0f);
        float a   = -LOG2E / (sig * sig);
        s_abc[tid] = make_float4(a, -2.0f * mu * a, a * mu * mu, 0.0f);
    }
    if (tid < 12) s_coord[tid] = coords[tid];
    if (tid < 4)  s_chg[tid]   = charges[tid];
    if (tid < HIDDEN) { s_b1[tid] = b1[tid]; s_b2[tid] = b2[tid]; s_w3[tid] = W3[tid]; }
    if (tid == 0) s_b3[0] = b3[0];
    if (tid < N_EE) {
        int rem = tid, i = 0, span = N_EL - 1;
        while (rem >= span) { rem -= span; span--; i++; }
        s_pi[tid] = i; s_pj[tid] = i + 1 + rem;
    }
    for (int idx = tid; idx < ROWS * 48; idx += THREADS) {
        int row = idx / 48, c = idx % 48;
        s_rs[row * 49 + c] = rs[(size_t)(b0 + row) * 48 + c];
    }
    __syncthreads();

    // ---- producer mappings ----
    const int rowA = tid >> 1;                  // A: row
    const int prA  = tid & 1;                   // A: which pair of the chunk
    const int swA  = rowA & 7;
    const float* myr = s_rs + rowA * 49;
    const int kB = tid >> 3;                    // B: k row (0..63)
    const int gB = tid & 7;                     // B: col16 group
    const uint32_t colB = (uint32_t)((gB ^ (kB & 7)) << 4);

    // A producer: 1 dist + 8 ex2 + 1x STS.128 per group (4 groups)
    auto produceA = [&](int chunk, uint32_t bb) {
        int p = chunk * 2 + prA;
        float dx, dy, dz;
        if (p < N_EN) {
            int e = p >> 2, a = p & 3;
            dx = myr[e * 3 + 0] - s_coord[a * 3 + 0];
            dy = myr[e * 3 + 1] - s_coord[a * 3 + 1];
            dz = myr[e * 3 + 2] - s_coord[a * 3 + 2];
        } else {
            int q = p - N_EN;
            int ii = s_pi[q], jj = s_pj[q];
            dx = myr[ii * 3 + 0] - myr[jj * 3 + 0];
            dy = myr[ii * 3 + 1] - myr[jj * 3 + 1];
            dz = myr[ii * 3 + 2] - myr[jj * 3 + 2];
        }
        float d = sqrtf(dx * dx + dy * dy + dz * dz);

        char* arow = smem + bb + A_o + rowA * 128;
        #pragma unroll
        for (int g4 = 0; g4 < 4; ++g4) {
            int g  = prA * 4 + g4;
            int fb = g4 * 8;
            float v[8];
            #pragma unroll
            for (int j = 0; j < 8; ++j) {
                float4 cc = s_abc[fb + j];
                v[j] = ex2(fmaf(fmaf(d, cc.x, cc.y), d, cc.z));
            }
            uint32_t hp[4];
            #pragma unroll
            for (int t = 0; t < 4; ++t) hp[t] = packh2(v[2 * t], v[2 * t + 1]);
            uint32_t col = (uint32_t)((g ^ swA) << 4);
            *(uint4*)(arow + col) = make_uint4(hp[0], hp[1], hp[2], hp[3]);
        }
    };
    // B producer: 8 W values -> 1 STS.128
    auto produceB = [&](uint32_t bb, float4 w0, float4 w1) {
        uint32_t hp[4];
        hp[0] = packh2(w0.x, w0.y);
        hp[1] = packh2(w0.z, w0.w);
        hp[2] = packh2(w1.x, w1.y);
        hp[3] = packh2(w1.z, w1.w);
        char* brow = smem + bb + B_o + kB * 128;
        *(uint4*)(brow + colB) = make_uint4(hp[0], hp[1], hp[2], hp[3]);
    };

    // ldmatrix per-lane constants
    const int sw_l = lane & 7;
    const int hi4  = lane >> 4;
    const uint32_t arow_l = (uint32_t)((wr * 32 + (lane & 15)) * 128);
    const uint32_t brow_l = (uint32_t)((lane & 15) * 128);

    float acc[2][4][4];
    #pragma unroll
    for (int mt = 0; mt < 2; ++mt)
        #pragma unroll
        for (int nt = 0; nt < 4; ++nt)
            #pragma unroll
            for (int q = 0; q < 4; ++q) acc[mt][nt][q] = 0.0f;

    // ---- prologue: produce chunk 0 into buf0 ----
    {
        const float4* wrow = (const float4*)(W1 + (size_t)kB * HIDDEN + gB * 8);
        float4 w0 = wrow[0], w1 = wrow[1];
        produceA(0, 0);
        produceB(0, w0, w1);
    }
    __syncthreads();

    // ---- mainloop: one barrier per chunk, produce next while MMA current ----
    for (int chunk = 0; chunk < NCHUNK; ++chunk) {
        const uint32_t bbc = (uint32_t)(chunk & 1) * BUFSZ;
        const uint32_t bbn = bbc ^ BUFSZ;

        if (chunk + 1 < NCHUNK) {
            const float4* wrow = (const float4*)(W1
                + ((size_t)(chunk + 1) * CK + kB) * HIDDEN + gB * 8);
            float4 w0 = wrow[0], w1 = wrow[1];
            produceA(chunk + 1, bbn);
            produceB(bbn, w0, w1);
        }

        // ---- MMA on current buffer: warp owns 32 rows x 32 cols ----
        const uint32_t abase = sbase + bbc + A_o + arow_l;
        const uint32_t bbase = sbase + bbc + B_o + brow_l;
        #pragma unroll
        for (int ks = 0; ks < 4; ++ks) {
            uint32_t ac = (uint32_t)(((2 * ks + hi4) ^ sw_l) << 4);
            uint32_t ah[2][4];
            ldsm4(ah[0], abase + ac);
            ldsm4(ah[1], abase + 2048 + ac);                    // +16 rows
            uint32_t bh[2][4];
            #pragma unroll
            for (int j = 0; j < 2; ++j) {
                uint32_t bc = (uint32_t)(((2 * (jc * 2 + j) + hi4) ^ sw_l) << 4);
                ldsm4t(bh[j], bbase + ks * 2048 + bc);
            }
            // 8 independent MMAs (distinct accumulators)
            #pragma unroll
            for (int j = 0; j < 2; ++j)
                #pragma unroll
                for (int ht = 0; ht < 2; ++ht)
                    #pragma unroll
                    for (int mt = 0; mt < 2; ++mt)
                        mma16816(acc[mt][2 * j + ht], ah[mt], &bh[j][2 * ht]);
        }
        __syncthreads();
    }

    // ---- stage W2 + epilogue ssp(acc+b1) -> s_h (overlay buffers) ----
    {
        const float4* wg = (const float4*)W2;
        float4* ws = (float4*)s_w2;
        #pragma unroll
        for (int i = 0; i < 2; ++i) ws[tid + i * THREADS] = wg[tid + i * THREADS];
    }
    #pragma unroll
    for (int mt = 0; mt < 2; ++mt) {
        int r0 = wr * 32 + mt * 16 + (lane >> 2);
        #pragma unroll
        for (int nt = 0; nt < 4; ++nt) {
            int c0 = jc * 32 + (nt >> 1) * 16 + (nt & 1) * 8 + (lane & 3) * 2;
            s_h[r0 * 66 + c0]           = sspf(acc[mt][nt][0] + s_b1[c0]);
            s_h[r0 * 66 + c0 + 1]       = sspf(acc[mt][nt][1] + s_b1[c0 + 1]);
            s_h[(r0 + 8) * 66 + c0]     = sspf(acc[mt][nt][2] + s_b1[c0]);
            s_h[(r0 + 8) * 66 + c0 + 1] = sspf(acc[mt][nt][3] + s_b1[c0 + 1]);
        }
    }
    __syncthreads();

    // ---- layer 2/3: 2 threads per row (32 cols each) ----
    {
        const int r  = tid >> 1;
        const int hc = (tid & 1) * 32;
        float a2[32];
        #pragma unroll
        for (int c = 0; c < 32; ++c) a2[c] = 0.0f;
        const float* hrow = s_h + r * 66;
        #pragma unroll 2
        for (int k = 0; k < HIDDEN; ++k) {
            float a = hrow[k];
            const float4* w4 = (const float4*)(s_w2 + k * HIDDEN + hc);
            #pragma unroll
            for (int j = 0; j < 8; ++j) {
                float4 w = w4[j];
                a2[4 * j + 0] += a * w.x;
                a2[4 * j + 1] += a * w.y;
                a2[4 * j + 2] += a * w.z;
                a2[4 * j + 3] += a * w.w;
            }
        }
        float partial = 0.0f;
        #pragma unroll
        for (int c = 0; c < 32; ++c)
            partial += sspf(a2[c] + s_b2[hc + c]) * s_w3[hc + c];
        float other = __shfl_xor_sync(0xffffffffu, partial, 1);
        if ((tid & 1) == 0) {
            float ys = partial + other + s_b3[0];
            const float* rr = s_rs + r * 49;
            float S = 0.0f;
            #pragma unroll 4
            for (int e = 0; e < N_EL; ++e) {
                float ex_ = rr[e * 3 + 0], ey = rr[e * 3 + 1], ez = rr[e * 3 + 2];
                #pragma unroll
                for (int a = 0; a < N_NUC; ++a) {
                    float dx = ex_ - s_coord[a * 3 + 0];
                    float dy = ey - s_coord[a * 3 + 1];
                    float dz = ez - s_coord[a * 3 + 2];
                    float dd = sqrtf(dx * dx + dy * dy + dz * dz);
                    S += (s_chg[a] * dd + dd * dd) / (1.0f + dd);
                }
            }
            out[b0 + r] = expf(ys) * expf(-S);
        }
    }
}

extern "C" void kernel_launch(void* const* d_in, const int* in_sizes, int n_in,
                              void* d_out, int out_size)
{
    const float* rs      = (const float*)d_in[0];
    const float* coords  = (const float*)d_in[1];
    const float* charges = (const float*)d_in[2];
    const float* W1      = (const float*)d_in[3];
    const float* b1      = (const float*)d_in[4];
    const float* W2      = (const float*)d_in[5];
    const float* b2      = (const float*)d_in[6];
    const float* W3      = (const float*)d_in[7];
    const float* b3      = (const float*)d_in[8];
    float* out = (float*)d_out;

    int batch = in_sizes[0] / (N_EL * 3);
    int grid  = batch / ROWS;

    cudaFuncSetAttribute(wfnet_kernel,
                         cudaFuncAttributeMaxDynamicSharedMemorySize, SMEM_BYTES);
    wfnet_kernel<<<grid, THREADS, SMEM_BYTES>>>(rs, coords, charges,
                                                W1, b1, W2, b2, W3, b3, out);
}

// round 16
// speedup vs baseline: 1.7915x; 1.0955x over previous
#include <cuda_runtime.h>
#include <cuda_fp16.h>
#include <math.h>
#include <stdint.h>

#define N_EL    16
#define N_NUC   4
#define N_FEATS 32
#define N_EN    64
#define N_EE    120
#define N_PAIRS 184
#define HIDDEN  64
#define ROWS    256
#define THREADS 512
#define CK      64
#define NCHUNK  92
#define NITER   46                 // two chunks per barrier

// ---- SMEM layout (bytes) ----
// Each buffer holds TWO chunks: A0,A1 (32KB each), B0,B1 (8KB each) = 81920
#define BUFSZ   81920
#define A0_o    0
#define A1_o    32768
#define B0_o    65536
#define B1_o    73728
#define OFF_RS  163840             // 256*49*4 = 50176
#define OFF_W2  81920              // overlay on buf1 after mainloop (16384)
#define OFF_H   0                  // overlay on buf0 after mainloop (256*66*4)
#define OFF_ABC   214016           // 32 x float4
#define OFF_COORD 214528
#define OFF_CHG   214576
#define OFF_B1    214592
#define OFF_B2    214848
#define OFF_W3    215104
#define OFF_B3    215360
#define OFF_PI    215376
#define OFF_PJ    215856
#define SMEM_BYTES 216336

#define LOG2E 1.4426950408889634f

__device__ __forceinline__ float sspf(float x) {
    return fmaxf(x, 0.0f) + log1pf(expf(-fabsf(x))) - 0.69314718055994531f;
}
__device__ __forceinline__ float ex2(float x) {
    float r; asm("ex2.approx.ftz.f32 %0, %1;" : "=f"(r) : "f"(x)); return r;
}
__device__ __forceinline__ uint32_t smem_u32(const void* p) {
    uint32_t a;
    asm("{ .reg .u64 t; cvta.to.shared.u64 t, %1; cvt.u32.u64 %0, t; }"
        : "=r"(a) : "l"(p));
    return a;
}
__device__ __forceinline__ void ldsm4(uint32_t* r, uint32_t a) {
    asm volatile("ldmatrix.sync.aligned.m8n8.x4.shared.b16 {%0,%1,%2,%3}, [%4];"
        : "=r"(r[0]), "=r"(r[1]), "=r"(r[2]), "=r"(r[3]) : "r"(a));
}
__device__ __forceinline__ void ldsm4t(uint32_t* r, uint32_t a) {
    asm volatile("ldmatrix.sync.aligned.m8n8.x4.trans.shared.b16 {%0,%1,%2,%3}, [%4];"
        : "=r"(r[0]), "=r"(r[1]), "=r"(r[2]), "=r"(r[3]) : "r"(a));
}
__device__ __forceinline__ void mma16816(float* c, const uint32_t* a, const uint32_t* b) {
    asm volatile("mma.sync.aligned.m16n8k16.row.col.f32.f16.f16.f32 "
        "{%0,%1,%2,%3}, {%4,%5,%6,%7}, {%8,%9}, {%0,%1,%2,%3};"
        : "+f"(c[0]), "+f"(c[1]), "+f"(c[2]), "+f"(c[3])
        : "r"(a[0]), "r"(a[1]), "r"(a[2]), "r"(a[3]), "r"(b[0]), "r"(b[1]));
}
__device__ __forceinline__ uint32_t packh2(float a, float b) {
    __half2 h = __floats2half2_rn(a, b);
    return *reinterpret_cast<uint32_t*>(&h);
}

__global__ __launch_bounds__(THREADS, 1)
void wfnet_kernel(const float* __restrict__ rs,
                  const float* __restrict__ coords,
                  const float* __restrict__ charges,
                  const float* __restrict__ W1,
                  const float* __restrict__ b1,
                  const float* __restrict__ W2,
                  const float* __restrict__ b2,
                  const float* __restrict__ W3,
                  const float* __restrict__ b3,
                  float* __restrict__ out)
{
    extern __shared__ char smem[];
    const uint32_t sbase = smem_u32(smem);

    float4* s_abc  = (float4*)(smem + OFF_ABC);
    float* s_coord = (float*)(smem + OFF_COORD);
    float* s_chg   = (float*)(smem + OFF_CHG);
    float* s_b1    = (float*)(smem + OFF_B1);
    float* s_b2    = (float*)(smem + OFF_B2);
    float* s_w3    = (float*)(smem + OFF_W3);
    float* s_b3    = (float*)(smem + OFF_B3);
    int*   s_pi    = (int*)  (smem + OFF_PI);
    int*   s_pj    = (int*)  (smem + OFF_PJ);
    float* s_rs    = (float*)(smem + OFF_RS);
    float* s_w2    = (float*)(smem + OFF_W2);
    float* s_h     = (float*)(smem + OFF_H);

    const int tid  = threadIdx.x;
    const int b0   = blockIdx.x * ROWS;
    const int lane = tid & 31;
    const int warp = tid >> 5;
    const int wr   = warp >> 1;          // row group: rows wr*32..+32
    const int jc   = warp & 1;           // col half:  cols jc*32..+32

    // ---- setup ----
    if (tid < N_FEATS) {
        float q   = (float)tid / 31.0f;
        float mu  = 10.0f * q * q;
        float sig = (1.0f + 10.0f * q) * (1.0f / 7.0f);
        float a   = -LOG2E / (sig * sig);
        s_abc[tid] = make_float4(a, -2.0f * mu * a, a * mu * mu, 0.0f);
    }
    if (tid < 12) s_coord[tid] = coords[tid];
    if (tid < 4)  s_chg[tid]   = charges[tid];
    if (tid < HIDDEN) { s_b1[tid] = b1[tid]; s_b2[tid] = b2[tid]; s_w3[tid] = W3[tid]; }
    if (tid == 0) s_b3[0] = b3[0];
    if (tid < N_EE) {
        int rem = tid, i = 0, span = N_EL - 1;
        while (rem >= span) { rem -= span; span--; i++; }
        s_pi[tid] = i; s_pj[tid] = i + 1 + rem;
    }
    for (int idx = tid; idx < ROWS * 48; idx += THREADS) {
        int row = idx / 48, c = idx % 48;
        s_rs[row * 49 + c] = rs[(size_t)(b0 + row) * 48 + c];
    }
    __syncthreads();

    // ---- producer mappings ----
    // A: thread owns 4 rows x 8 feats x 1 pair
    const int fgA   = tid & 3;               // feature group (8 feats)
    const int prA2  = (tid >> 2) & 1;        // pair of chunk
    const int rbase = (tid >> 3) * 4;        // rows rbase..rbase+3
    // coefficients in registers (loaded once)
    float cA[8], cB[8], cC[8];
    #pragma unroll
    for (int j = 0; j < 8; ++j) {
        float4 cc = s_abc[fgA * 8 + j];
        cA[j] = cc.x; cB[j] = cc.y; cC[j] = cc.z;
    }
    // B: thread owns k row kB, col16 group gB
    const int kB = tid >> 3;
    const int gB = tid & 7;
    const uint32_t colB = (uint32_t)((gB ^ (kB & 7)) << 4);

    auto produceA = [&](int chunk, uint32_t abuf) {
        int p = chunk * 2 + prA2;
        float cx = 0.f, cy = 0.f, cz = 0.f;
        int e0, e1 = -1;
        if (p < N_EN) {
            e0 = p >> 2; int a = p & 3;
            cx = s_coord[a * 3 + 0]; cy = s_coord[a * 3 + 1]; cz = s_coord[a * 3 + 2];
        } else {
            e0 = s_pi[p - N_EN]; e1 = s_pj[p - N_EN];
        }
        const int g = prA2 * 4 + fgA;
        #pragma unroll
        for (int rr = 0; rr < 4; ++rr) {
            int r = rbase + rr;
            const float* rrow = s_rs + r * 49;
            float dx, dy, dz;
            if (e1 < 0) {
                dx = rrow[e0 * 3 + 0] - cx;
                dy = rrow[e0 * 3 + 1] - cy;
                dz = rrow[e0 * 3 + 2] - cz;
            } else {
                dx = rrow[e0 * 3 + 0] - rrow[e1 * 3 + 0];
                dy = rrow[e0 * 3 + 1] - rrow[e1 * 3 + 1];
                dz = rrow[e0 * 3 + 2] - rrow[e1 * 3 + 2];
            }
            float d = sqrtf(dx * dx + dy * dy + dz * dz);
            float v[8];
            #pragma unroll
            for (int j = 0; j < 8; ++j)
                v[j] = ex2(fmaf(fmaf(d, cA[j], cB[j]), d, cC[j]));
            uint32_t hp[4];
            #pragma unroll
            for (int t = 0; t < 4; ++t) hp[t] = packh2(v[2 * t], v[2 * t + 1]);
            uint32_t col = (uint32_t)((g ^ (r & 7)) << 4);
            *(uint4*)(smem + abuf + r * 128 + col) = make_uint4(hp[0], hp[1], hp[2], hp[3]);
        }
    };
    auto produceB = [&](uint32_t bbuf, float4 w0, float4 w1) {
        uint32_t hp[4];
        hp[0] = packh2(w0.x, w0.y);
        hp[1] = packh2(w0.z, w0.w);
        hp[2] = packh2(w1.x, w1.y);
        hp[3] = packh2(w1.z, w1.w);
        *(uint4*)(smem + bbuf + kB * 128 + colB) = make_uint4(hp[0], hp[1], hp[2], hp[3]);
    };

    // ldmatrix per-lane constants
    const int sw_l = lane & 7;
    const int hi4  = lane >> 4;
    const uint32_t arow_l = (uint32_t)((wr * 32 + (lane & 15)) * 128);
    const uint32_t brow_l = (uint32_t)((lane & 15) * 128);

    float acc[2][4][4];
    #pragma unroll
    for (int mt = 0; mt < 2; ++mt)
        #pragma unroll
        for (int nt = 0; nt < 4; ++nt)
            #pragma unroll
            for (int q = 0; q < 4; ++q) acc[mt][nt][q] = 0.0f;

    // ---- prologue: produce chunks 0,1 into buf0 ----
    {
        float4 w[2][2];
        #pragma unroll
        for (int s = 0; s < 2; ++s) {
            const float4* wrow = (const float4*)(W1 + ((size_t)s * CK + kB) * HIDDEN + gB * 8);
            w[s][0] = wrow[0]; w[s][1] = wrow[1];
        }
        produceA(0, A0_o);
        produceA(1, A1_o);
        produceB(B0_o, w[0][0], w[0][1]);
        produceB(B1_o, w[1][0], w[1][1]);
    }
    __syncthreads();

    // ---- mainloop: one barrier per 2 chunks ----
    for (int it = 0; it < NITER; ++it) {
        const uint32_t bbc = (uint32_t)(it & 1) * BUFSZ;
        const uint32_t bbn = bbc ^ BUFSZ;

        if (it + 1 < NITER) {
            float4 w[2][2];
            #pragma unroll
            for (int s = 0; s < 2; ++s) {
                int ch = 2 * (it + 1) + s;
                const float4* wrow = (const float4*)(W1
                    + ((size_t)ch * CK + kB) * HIDDEN + gB * 8);
                w[s][0] = wrow[0]; w[s][1] = wrow[1];
            }
            produceA(2 * (it + 1) + 0, bbn + A0_o);
            produceA(2 * (it + 1) + 1, bbn + A1_o);
            produceB(bbn + B0_o, w[0][0], w[0][1]);
            produceB(bbn + B1_o, w[1][0], w[1][1]);
        }

        // ---- MMA on both sub-chunks of current buffer ----
        #pragma unroll
        for (int s = 0; s < 2; ++s) {
            const uint32_t abase = sbase + bbc + (s ? A1_o : A0_o) + arow_l;
            const uint32_t bbase = sbase + bbc + (s ? B1_o : B0_o) + brow_l;
            #pragma unroll
            for (int ks = 0; ks < 4; ++ks) {
                uint32_t ac = (uint32_t)(((2 * ks + hi4) ^ sw_l) << 4);
                uint32_t ah[2][4];
                ldsm4(ah[0], abase + ac);
                ldsm4(ah[1], abase + 2048 + ac);                // +16 rows
                uint32_t bh[2][4];
                #pragma unroll
                for (int j = 0; j < 2; ++j) {
                    uint32_t bc = (uint32_t)(((2 * (jc * 2 + j) + hi4) ^ sw_l) << 4);
                    ldsm4t(bh[j], bbase + ks * 2048 + bc);
                }
                #pragma unroll
                for (int j = 0; j < 2; ++j)
                    #pragma unroll
                    for (int ht = 0; ht < 2; ++ht)
                        #pragma unroll
                        for (int mt = 0; mt < 2; ++mt)
                            mma16816(acc[mt][2 * j + ht], ah[mt], &bh[j][2 * ht]);
            }
        }
        __syncthreads();
    }

    // ---- stage W2 (overlay buf1) + epilogue ssp(acc+b1) -> s_h (overlay buf0) ----
    {
        const float4* wg = (const float4*)W2;
        float4* ws = (float4*)s_w2;
        #pragma unroll
        for (int i = 0; i < 2; ++i) ws[tid + i * THREADS] = wg[tid + i * THREADS];
    }
    #pragma unroll
    for (int mt = 0; mt < 2; ++mt) {
        int r0 = wr * 32 + mt * 16 + (lane >> 2);
        #pragma unroll
        for (int nt = 0; nt < 4; ++nt) {
            int c0 = jc * 32 + (nt >> 1) * 16 + (nt & 1) * 8 + (lane & 3) * 2;
            s_h[r0 * 66 + c0]           = sspf(acc[mt][nt][0] + s_b1[c0]);
            s_h[r0 * 66 + c0 + 1]       = sspf(acc[mt][nt][1] + s_b1[c0 + 1]);
            s_h[(r0 + 8) * 66 + c0]     = sspf(acc[mt][nt][2] + s_b1[c0]);
            s_h[(r0 + 8) * 66 + c0 + 1] = sspf(acc[mt][nt][3] + s_b1[c0 + 1]);
        }
    }
    __syncthreads();

    // ---- layer 2/3: 2 threads per row (32 cols each) ----
    {
        const int r  = tid >> 1;
        const int hc = (tid & 1) * 32;
        float a2[32];
        #pragma unroll
        for (int c = 0; c < 32; ++c) a2[c] = 0.0f;
        const float* hrow = s_h + r * 66;
        #pragma unroll 2
        for (int k = 0; k < HIDDEN; ++k) {
            float a = hrow[k];
            const float4* w4 = (const float4*)(s_w2 + k * HIDDEN + hc);
            #pragma unroll
            for (int j = 0; j < 8; ++j) {
                float4 w = w4[j];
                a2[4 * j + 0] += a * w.x;
                a2[4 * j + 1] += a * w.y;
                a2[4 * j + 2] += a * w.z;
                a2[4 * j + 3] += a * w.w;
            }
        }
        float partial = 0.0f;
        #pragma unroll
        for (int c = 0; c < 32; ++c)
            partial += sspf(a2[c] + s_b2[hc + c]) * s_w3[hc + c];
        float other = __shfl_xor_sync(0xffffffffu, partial, 1);
        if ((tid & 1) == 0) {
            float ys = partial + other + s_b3[0];
            const float* rr = s_rs + r * 49;
            float S = 0.0f;
            #pragma unroll 4
            for (int e = 0; e < N_EL; ++e) {
                float ex_ = rr[e * 3 + 0], ey = rr[e * 3 + 1], ez = rr[e * 3 + 2];
                #pragma unroll
                for (int a = 0; a < N_NUC; ++a) {
                    float dx = ex_ - s_coord[a * 3 + 0];
                    float dy = ey - s_coord[a * 3 + 1];
                    float dz = ez - s_coord[a * 3 + 2];
                    float dd = sqrtf(dx * dx + dy * dy + dz * dz);
                    S += (s_chg[a] * dd + dd * dd) / (1.0f + dd);
                }
            }
            out[b0 + r] = expf(ys) * expf(-S);
        }
    }
}

extern "C" void kernel_launch(void* const* d_in, const int* in_sizes, int n_in,
                              void* d_out, int out_size)
{
    const float* rs      = (const float*)d_in[0];
    const float* coords  = (const float*)d_in[1];
    const float* charges = (const float*)d_in[2];
    const float* W1      = (const float*)d_in[3];
    const float* b1      = (const float*)d_in[4];
    const float* W2      = (const float*)d_in[5];
    const float* b2      = (const float*)d_in[6];
    const float* W3      = (const float*)d_in[7];
    const float* b3      = (const float*)d_in[8];
    float* out = (float*)d_out;

    int batch = in_sizes[0] / (N_EL * 3);
    int grid  = batch / ROWS;

    cudaFuncSetAttribute(wfnet_kernel,
                         cudaFuncAttributeMaxDynamicSharedMemorySize, SMEM_BYTES);
    wfnet_kernel<<<grid, THREADS, SMEM_BYTES>>>(rs, coords, charges,
                                                W1, b1, W2, b2, W3, b3, out);
}

// round 17
// speedup vs baseline: 1.9229x; 1.0734x over previous
#include <cuda_runtime.h>
#include <cuda_fp16.h>
#include <math.h>
#include <stdint.h>

#define N_EL    16
#define N_NUC   4
#define N_FEATS 32
#define N_EN    64
#define N_EE    120
#define N_PAIRS 184
#define HIDDEN  64
#define ROWS    256
#define THREADS 512
#define CK      64
#define NCHUNK  92
#define NITER   46                 // two chunks per barrier

// W1 pre-converted to fp16, pre-swizzled into B-tile layout (uint4 units)
#define W1H_U4  (N_PAIRS * N_FEATS * HIDDEN * 2 / 16)   // 47104
__device__ uint4 g_W1h[W1H_U4];

// ---- SMEM layout (bytes) ----
#define BUFSZ   81920
#define A0_o    0
#define A1_o    32768
#define B0_o    65536
#define B1_o    73728
#define OFF_RS  163840             // 256*49*4 = 50176
#define OFF_W2  81920              // overlay on buf1 after mainloop (16384)
#define OFF_H   0                  // overlay on buf0 after mainloop (256*66*4)
#define OFF_ABC   214016           // 32 x float4
#define OFF_COORD 214528
#define OFF_CHG   214576
#define OFF_B1    214592
#define OFF_B2    214848
#define OFF_W3    215104
#define OFF_B3    215360
#define OFF_PI    215376
#define OFF_PJ    215856
#define SMEM_BYTES 216336

#define LOG2E 1.4426950408889634f

__device__ __forceinline__ float sspf(float x) {
    return fmaxf(x, 0.0f) + log1pf(expf(-fabsf(x))) - 0.69314718055994531f;
}
__device__ __forceinline__ uint32_t smem_u32(const void* p) {
    uint32_t a;
    asm("{ .reg .u64 t; cvta.to.shared.u64 t, %1; cvt.u32.u64 %0, t; }"
        : "=r"(a) : "l"(p));
    return a;
}
__device__ __forceinline__ void ldsm4(uint32_t* r, uint32_t a) {
    asm volatile("ldmatrix.sync.aligned.m8n8.x4.shared.b16 {%0,%1,%2,%3}, [%4];"
        : "=r"(r[0]), "=r"(r[1]), "=r"(r[2]), "=r"(r[3]) : "r"(a));
}
__device__ __forceinline__ void ldsm4t(uint32_t* r, uint32_t a) {
    asm volatile("ldmatrix.sync.aligned.m8n8.x4.trans.shared.b16 {%0,%1,%2,%3}, [%4];"
        : "=r"(r[0]), "=r"(r[1]), "=r"(r[2]), "=r"(r[3]) : "r"(a));
}
__device__ __forceinline__ void mma16816(float* c, const uint32_t* a, const uint32_t* b) {
    asm volatile("mma.sync.aligned.m16n8k16.row.col.f32.f16.f16.f32 "
        "{%0,%1,%2,%3}, {%4,%5,%6,%7}, {%8,%9}, {%0,%1,%2,%3};"
        : "+f"(c[0]), "+f"(c[1]), "+f"(c[2]), "+f"(c[3])
        : "r"(a[0]), "r"(a[1]), "r"(a[2]), "r"(a[3]), "r"(b[0]), "r"(b[1]));
}
__device__ __forceinline__ uint32_t packh2(float a, float b) {
    __half2 h = __floats2half2_rn(a, b);
    return *reinterpret_cast<uint32_t*>(&h);
}
// dual fp16 exp2 on MUFU: in = packed fp16x2 args, out = packed fp16x2 exp2
__device__ __forceinline__ uint32_t ex2h2(uint32_t in) {
    uint32_t r;
    asm("ex2.approx.f16x2 %0, %1;" : "=r"(r) : "r"(in));
    return r;
}
__device__ __forceinline__ void cpasync16(uint32_t dst, const uint4* src) {
    asm volatile("cp.async.cg.shared.global [%0], [%1], 16;"
                 :: "r"(dst), "l"(__cvta_generic_to_global(src)) : "memory");
}

// ---- one-shot W1 -> fp16 swizzled-B-layout conversion ----
__global__ void convert_w1_kernel(const float* __restrict__ W1) {
    int t = blockIdx.x * 256 + threadIdx.x;       // one per 8-value group
    if (t >= W1H_U4) return;
    int kk = t >> 3, g = t & 7;
    const float4* wrow = (const float4*)(W1 + (size_t)kk * HIDDEN + g * 8);
    float4 w0 = wrow[0], w1 = wrow[1];
    uint4 v;
    v.x = packh2(w0.x, w0.y); v.y = packh2(w0.z, w0.w);
    v.z = packh2(w1.x, w1.y); v.w = packh2(w1.z, w1.w);
    g_W1h[(uint32_t)kk * 8 + (uint32_t)(g ^ (kk & 7))] = v;
}

__global__ __launch_bounds__(THREADS, 1)
void wfnet_kernel(const float* __restrict__ rs,
                  const float* __restrict__ coords,
                  const float* __restrict__ charges,
                  const float* __restrict__ b1,
                  const float* __restrict__ W2,
                  const float* __restrict__ b2,
                  const float* __restrict__ W3,
                  const float* __restrict__ b3,
                  float* __restrict__ out)
{
    extern __shared__ char smem[];
    const uint32_t sbase = smem_u32(smem);

    float4* s_abc  = (float4*)(smem + OFF_ABC);
    float* s_coord = (float*)(smem + OFF_COORD);
    float* s_chg   = (float*)(smem + OFF_CHG);
    float* s_b1    = (float*)(smem + OFF_B1);
    float* s_b2    = (float*)(smem + OFF_B2);
    float* s_w3    = (float*)(smem + OFF_W3);
    float* s_b3    = (float*)(smem + OFF_B3);
    int*   s_pi    = (int*)  (smem + OFF_PI);
    int*   s_pj    = (int*)  (smem + OFF_PJ);
    float* s_rs    = (float*)(smem + OFF_RS);
    float* s_w2    = (float*)(smem + OFF_W2);
    float* s_h     = (float*)(smem + OFF_H);

    const int tid  = threadIdx.x;
    const int b0   = blockIdx.x * ROWS;
    const int lane = tid & 31;
    const int warp = tid >> 5;
    const int wr   = warp >> 1;          // rows wr*32..+32
    const int jc   = warp & 1;           // cols jc*32..+32

    // ---- setup ----
    if (tid < N_FEATS) {
        float q   = (float)tid / 31.0f;
        float mu  = 10.0f * q * q;
        float sig = (1.0f + 10.0f * q) * (1.0f / 7.0f);
        float a   = -LOG2E / (sig * sig);
        s_abc[tid] = make_float4(a, -2.0f * mu * a, a * mu * mu, 0.0f);
    }
    if (tid < 12) s_coord[tid] = coords[tid];
    if (tid < 4)  s_chg[tid]   = charges[tid];
    if (tid < HIDDEN) { s_b1[tid] = b1[tid]; s_b2[tid] = b2[tid]; s_w3[tid] = W3[tid]; }
    if (tid == 0) s_b3[0] = b3[0];
    if (tid < N_EE) {
        int rem = tid, i = 0, span = N_EL - 1;
        while (rem >= span) { rem -= span; span--; i++; }
        s_pi[tid] = i; s_pj[tid] = i + 1 + rem;
    }
    for (int idx = tid; idx < ROWS * 48; idx += THREADS) {
        int row = idx / 48, c = idx % 48;
        s_rs[row * 49 + c] = rs[(size_t)(b0 + row) * 48 + c];
    }
    __syncthreads();

    // ---- producer mappings ----
    // A: thread owns 4 rows x 8 feats x 1 pair
    const int fgA   = tid & 3;               // feature group (8 feats)
    const int prA2  = (tid >> 2) & 1;        // pair of chunk
    const int rbase = (tid >> 3) * 4;        // rows rbase..rbase+3
    float cA[8], cB[8], cC[8];
    #pragma unroll
    for (int j = 0; j < 8; ++j) {
        float4 cc = s_abc[fgA * 8 + j];
        cA[j] = cc.x; cB[j] = cc.y; cC[j] = cc.z;
    }

    auto produceA = [&](int chunk, uint32_t abuf) {
        int p = chunk * 2 + prA2;
        float cx = 0.f, cy = 0.f, cz = 0.f;
        int e0, e1 = -1;
        if (p < N_EN) {
            e0 = p >> 2; int a = p & 3;
            cx = s_coord[a * 3 + 0]; cy = s_coord[a * 3 + 1]; cz = s_coord[a * 3 + 2];
        } else {
            e0 = s_pi[p - N_EN]; e1 = s_pj[p - N_EN];
        }
        const int g = prA2 * 4 + fgA;
        #pragma unroll
        for (int rr = 0; rr < 4; ++rr) {
            int r = rbase + rr;
            const float* rrow = s_rs + r * 49;
            float dx, dy, dz;
            if (e1 < 0) {
                dx = rrow[e0 * 3 + 0] - cx;
                dy = rrow[e0 * 3 + 1] - cy;
                dz = rrow[e0 * 3 + 2] - cz;
            } else {
                dx = rrow[e0 * 3 + 0] - rrow[e1 * 3 + 0];
                dy = rrow[e0 * 3 + 1] - rrow[e1 * 3 + 1];
                dz = rrow[e0 * 3 + 2] - rrow[e1 * 3 + 2];
            }
            float d = sqrtf(dx * dx + dy * dy + dz * dz);
            uint32_t hp[4];
            #pragma unroll
            for (int t = 0; t < 4; ++t) {
                float a0 = fmaf(fmaf(d, cA[2 * t],     cB[2 * t]),     d, cC[2 * t]);
                float a1 = fmaf(fmaf(d, cA[2 * t + 1], cB[2 * t + 1]), d, cC[2 * t + 1]);
                hp[t] = ex2h2(packh2(a0, a1));
            }
            uint32_t col = (uint32_t)((g ^ (r & 7)) << 4);
            *(uint4*)(smem + abuf + r * 128 + col) = make_uint4(hp[0], hp[1], hp[2], hp[3]);
        }
    };
    // B staging: one cp.async.cg 16B per thread per chunk (pre-swizzled fp16)
    auto stageB = [&](int chunk, uint32_t bbuf) {
        cpasync16(sbase + bbuf + (uint32_t)tid * 16, g_W1h + (size_t)chunk * 512 + tid);
    };

    // ldmatrix per-lane constants
    const int sw_l = lane & 7;
    const int hi4  = lane >> 4;
    const uint32_t arow_l = (uint32_t)((wr * 32 + (lane & 15)) * 128);
    const uint32_t brow_l = (uint32_t)((lane & 15) * 128);

    float acc[2][4][4];
    #pragma unroll
    for (int mt = 0; mt < 2; ++mt)
        #pragma unroll
        for (int nt = 0; nt < 4; ++nt)
            #pragma unroll
            for (int q = 0; q < 4; ++q) acc[mt][nt][q] = 0.0f;

    // ---- prologue: stage chunks 0,1 into buf0 ----
    stageB(0, B0_o);
    stageB(1, B1_o);
    asm volatile("cp.async.commit_group;" ::: "memory");
    produceA(0, A0_o);
    produceA(1, A1_o);
    asm volatile("cp.async.wait_group 0;" ::: "memory");
    __syncthreads();

    // ---- mainloop: one barrier per 2 chunks ----
    for (int it = 0; it < NITER; ++it) {
        const uint32_t bbc = (uint32_t)(it & 1) * BUFSZ;
        const uint32_t bbn = bbc ^ BUFSZ;

        if (it + 1 < NITER) {
            stageB(2 * (it + 1) + 0, bbn + B0_o);
            stageB(2 * (it + 1) + 1, bbn + B1_o);
            asm volatile("cp.async.commit_group;" ::: "memory");
            produceA(2 * (it + 1) + 0, bbn + A0_o);
            produceA(2 * (it + 1) + 1, bbn + A1_o);
        }

        // ---- MMA on both sub-chunks of current buffer ----
        #pragma unroll
        for (int s = 0; s < 2; ++s) {
            const uint32_t abase = sbase + bbc + (s ? A1_o : A0_o) + arow_l;
            const uint32_t bbase = sbase + bbc + (s ? B1_o : B0_o) + brow_l;
            #pragma unroll
            for (int ks = 0; ks < 4; ++ks) {
                uint32_t ac = (uint32_t)(((2 * ks + hi4) ^ sw_l) << 4);
                uint32_t ah[2][4];
                ldsm4(ah[0], abase + ac);
                ldsm4(ah[1], abase + 2048 + ac);                // +16 rows
                uint32_t bh[2][4];
                #pragma unroll
                for (int j = 0; j < 2; ++j) {
                    uint32_t bc = (uint32_t)(((2 * (jc * 2 + j) + hi4) ^ sw_l) << 4);
                    ldsm4t(bh[j], bbase + ks * 2048 + bc);
                }
                #pragma unroll
                for (int j = 0; j < 2; ++j)
                    #pragma unroll
                    for (int ht = 0; ht < 2; ++ht)
                        #pragma unroll
                        for (int mt = 0; mt < 2; ++mt)
                            mma16816(acc[mt][2 * j + ht], ah[mt], &bh[j][2 * ht]);
            }
        }
        asm volatile("cp.async.wait_group 0;" ::: "memory");
        __syncthreads();
    }

    // ---- stage W2 (overlay buf1) + epilogue ssp(acc+b1) -> s_h (overlay buf0) ----
    {
        const float4* wg = (const float4*)W2;
        float4* ws = (float4*)s_w2;
        #pragma unroll
        for (int i = 0; i < 2; ++i) ws[tid + i * THREADS] = wg[tid + i * THREADS];
    }
    #pragma unroll
    for (int mt = 0; mt < 2; ++mt) {
        int r0 = wr * 32 + mt * 16 + (lane >> 2);
        #pragma unroll
        for (int nt = 0; nt < 4; ++nt) {
            int c0 = jc * 32 + (nt >> 1) * 16 + (nt & 1) * 8 + (lane & 3) * 2;
            s_h[r0 * 66 + c0]           = sspf(acc[mt][nt][0] + s_b1[c0]);
            s_h[r0 * 66 + c0 + 1]       = sspf(acc[mt][nt][1] + s_b1[c0 + 1]);
            s_h[(r0 + 8) * 66 + c0]     = sspf(acc[mt][nt][2] + s_b1[c0]);
            s_h[(r0 + 8) * 66 + c0 + 1] = sspf(acc[mt][nt][3] + s_b1[c0 + 1]);
        }
    }
    __syncthreads();

    // ---- layer 2/3: 2 threads per row (32 cols each) ----
    {
        const int r  = tid >> 1;
        const int hc = (tid & 1) * 32;
        float a2[32];
        #pragma unroll
        for (int c = 0; c < 32; ++c) a2[c] = 0.0f;
        const float* hrow = s_h + r * 66;
        #pragma unroll 2
        for (int k = 0; k < HIDDEN; ++k) {
            float a = hrow[k];
            const float4* w4 = (const float4*)(s_w2 + k * HIDDEN + hc);
            #pragma unroll
            for (int j = 0; j < 8; ++j) {
                float4 w = w4[j];
                a2[4 * j + 0] += a * w.x;
                a2[4 * j + 1] += a * w.y;
                a2[4 * j + 2] += a * w.z;
                a2[4 * j + 3] += a * w.w;
            }
        }
        float partial = 0.0f;
        #pragma unroll
        for (int c = 0; c < 32; ++c)
            partial += sspf(a2[c] + s_b2[hc + c]) * s_w3[hc + c];
        float other = __shfl_xor_sync(0xffffffffu, partial, 1);
        if ((tid & 1) == 0) {
            float ys = partial + other + s_b3[0];
            const float* rr = s_rs + r * 49;
            float S = 0.0f;
            #pragma unroll 4
            for (int e = 0; e < N_EL; ++e) {
                float ex_ = rr[e * 3 + 0], ey = rr[e * 3 + 1], ez = rr[e * 3 + 2];
                #pragma unroll
                for (int a = 0; a < N_NUC; ++a) {
                    float dx = ex_ - s_coord[a * 3 + 0];
                    float dy = ey - s_coord[a * 3 + 1];
                    float dz = ez - s_coord[a * 3 + 2];
                    float dd = sqrtf(dx * dx + dy * dy + dz * dz);
                    S += (s_chg[a] * dd + dd * dd) / (1.0f + dd);
                }
            }
            out[b0 + r] = expf(ys) * expf(-S);
        }
    }
}

extern "C" void kernel_launch(void* const* d_in, const int* in_sizes, int n_in,
                              void* d_out, int out_size)
{
    const float* rs      = (const float*)d_in[0];
    const float* coords  = (const float*)d_in[1];
    const float* charges = (const float*)d_in[2];
    const float* W1      = (const float*)d_in[3];
    const float* b1      = (const float*)d_in[4];
    const float* W2      = (const float*)d_in[5];
    const float* b2      = (const float*)d_in[6];
    const float* W3      = (const float*)d_in[7];
    const float* b3      = (const float*)d_in[8];
    float* out = (float*)d_out;

    int batch = in_sizes[0] / (N_EL * 3);
    int grid  = batch / ROWS;

    convert_w1_kernel<<<(W1H_U4 + 255) / 256, 256>>>(W1);

    cudaFuncSetAttribute(wfnet_kernel,
                         cudaFuncAttributeMaxDynamicSharedMemorySize, SMEM_BYTES);
    wfnet_kernel<<<grid, THREADS, SMEM_BYTES>>>(rs, coords, charges,
                                                b1, W2, b2, W3, b3, out);
}